// round 14
// baseline (speedup 1.0000x reference)
#include <cuda_runtime.h>
#include <cstdint>

#define DIM 4096
typedef unsigned long long u64;

// 128 MB complex scratch for Y = x U^H (float4 => 16B aligned).
__device__ float4 g_buf[(size_t)DIM * DIM / 2];
// Unpacked gates [conj?][qubit][4]: float2 {re, im}  (used by kernelA stage 0)
__device__ float2 g_gates[2][12][4];
// Packed gates for f32x2 math: float4 {re, re, -im, +im} per element
__device__ float4 g_gpk[2][12][4];

// ---------------- f32x2 packed primitives (Blackwell FFMA2) ----------------
__device__ __forceinline__ u64 fma2(u64 a, u64 b, u64 c) {
    u64 d; asm("fma.rn.f32x2 %0, %1, %2, %3;" : "=l"(d) : "l"(a), "l"(b), "l"(c));
    return d;
}
__device__ __forceinline__ u64 mul2(u64 a, u64 b) {
    u64 d; asm("mul.rn.f32x2 %0, %1, %2;" : "=l"(d) : "l"(a), "l"(b));
    return d;
}
__device__ __forceinline__ u64 pack2(float lo, float hi) {
    u64 d; asm("mov.b64 %0, {%1, %2};" : "=l"(d) : "f"(lo), "f"(hi));
    return d;
}
__device__ __forceinline__ u64 swp2(u64 a) {
    unsigned lo, hi;
    asm("mov.b64 {%0, %1}, %2;" : "=r"(lo), "=r"(hi) : "l"(a));
    u64 d; asm("mov.b64 %0, {%1, %2};" : "=l"(d) : "r"(hi), "r"(lo));
    return d;
}
__device__ __forceinline__ float lo32(u64 a) {
    unsigned lo, hi;
    asm("mov.b64 {%0, %1}, %2;" : "=r"(lo), "=r"(hi) : "l"(a));
    return __uint_as_float(lo);
}

__device__ __forceinline__ float2 cmulh(float2 a, float2 b) {
    return make_float2(fmaf(a.x, b.x, -a.y * b.y), fmaf(a.x, b.y, a.y * b.x));
}

__device__ __forceinline__ int PHYS(int j) { return j ^ ((j >> 4) & 15); }

// ---------------------------------------------------------------------------
__global__ void prep_kernel(const float* __restrict__ w) {
    int q = threadIdx.x;
    if (q >= 12) return;
    const float WM = 0.63245553203367586640f;  // sqrt(2/5)
    float hx = 0.5f * w[3 * q + 0] * WM;
    float hy = 0.5f * w[3 * q + 1] * WM;
    float hz = 0.5f * w[3 * q + 2] * WM;
    float cx, sx, cy, sy, cz, sz;
    sincosf(hx, &sx, &cx);
    sincosf(hy, &sy, &cy);
    sincosf(hz, &sz, &cz);
    float2 m0 = make_float2(cy * cx, sy * sx);
    float2 m1 = make_float2(-sy * cx, -cy * sx);
    float2 m2 = make_float2(sy * cx, -cy * sx);
    float2 m3 = make_float2(cy * cx, -sy * sx);
    float2 ez  = make_float2(cz, -sz);
    float2 ezc = make_float2(cz,  sz);
    float2 u[4];
    u[0] = cmulh(ez, m0);  u[1] = cmulh(ez, m1);
    u[2] = cmulh(ezc, m2); u[3] = cmulh(ezc, m3);
#pragma unroll
    for (int e = 0; e < 4; e++) {
        g_gates[0][q][e] = u[e];
        g_gates[1][q][e] = make_float2(u[e].x, -u[e].y);
        g_gpk[0][q][e] = make_float4(u[e].x, u[e].x, -u[e].y,  u[e].y);
        g_gpk[1][q][e] = make_float4(u[e].x, u[e].x,  u[e].y, -u[e].y);
    }
}

// ---------------------------------------------------------------------------
// Packed butterfly stages s0..3 of pass `pass` on 16 packed complex values.
// Per pair: 8 fma-pipe slots (6xFMA2 + 2xMUL2) + 2 half-swaps (alu pipe).
// ---------------------------------------------------------------------------
__device__ __forceinline__ void bstages(u64 v[16], int pass, int cj, int s0) {
#pragma unroll
    for (int s = 0; s < 4; s++) {
        if (s < s0) continue;
        int q = 11 - (4 * pass + s);
        const ulonglong2* gp = (const ulonglong2*)g_gpk[cj][q];
        u64 gx0 = gp[0].x, gy0 = gp[0].y, gx1 = gp[1].x, gy1 = gp[1].y;
        u64 gx2 = gp[2].x, gy2 = gp[2].y, gx3 = gp[3].x, gy3 = gp[3].y;
        int str = 1 << s;
#pragma unroll
        for (int k = 0; k < 16; k++) {
            if ((k & str) == 0) {
                u64 a = v[k], b = v[k + str];
                u64 sa = swp2(a), sb = swp2(b);
                v[k]       = fma2(gx0, a, fma2(gy0, sa, fma2(gx1, b, mul2(gy1, sb))));
                v[k + str] = fma2(gx2, a, fma2(gy2, sa, fma2(gx3, b, mul2(gy3, sb))));
            }
        }
    }
}

// ---------------------------------------------------------------------------
// Kernel A: Y = x U^H, one ROW per CTA, 128 threads, 32KB smem.
// min 6 CTAs/SM -> ptxas caps regs (~85) -> 24 warps/SM for latency hiding.
// ---------------------------------------------------------------------------
__global__ void __launch_bounds__(128, 6) kernelA(const float* __restrict__ x) {
    extern __shared__ float2 smf[];
    u64* sm = (u64*)smf;                      // [DIM] packed complex
    const int t   = threadIdx.x;
    const int row = blockIdx.x;

    // ---- load + pass 0 (bits 0..3), conj gates ----
    const u64* ge = (const u64*)g_gates[1][11];   // stage 0 -> qubit 11
#pragma unroll
    for (int gi = 0; gi < 2; gi++) {
        int g = t + gi * 128;                 // group 0..255
        const float4* src = (const float4*)(x + (size_t)row * DIM + g * 16);
        float f[16];
#pragma unroll
        for (int i = 0; i < 4; i++) {
            float4 q4 = src[i];
            f[4 * i + 0] = q4.x; f[4 * i + 1] = q4.y;
            f[4 * i + 2] = q4.z; f[4 * i + 3] = q4.w;
        }
        u64 v[16];
        // real-input stage 0: pairs (2k, 2k+1)
#pragma unroll
        for (int k = 0; k < 16; k += 2) {
            u64 aa = pack2(f[k], f[k]);
            u64 bb = pack2(f[k + 1], f[k + 1]);
            v[k]     = fma2(ge[0], aa, mul2(ge[1], bb));
            v[k + 1] = fma2(ge[2], aa, mul2(ge[3], bb));
        }
        bstages(v, 0, 1, 1);                  // stages 1..3 of pass 0
#pragma unroll
        for (int i = 0; i < 16; i++) sm[PHYS(g * 16 + i)] = v[i];
    }
    __syncthreads();

    // ---- pass 1 (bits 4..7) ----
#pragma unroll
    for (int gi = 0; gi < 2; gi++) {
        int g = t + gi * 128;
        int base = ((g >> 4) << 8) + (g & 15);
        u64 v[16];
#pragma unroll
        for (int i = 0; i < 16; i++) v[i] = sm[PHYS(base + i * 16)];
        bstages(v, 1, 1, 0);
#pragma unroll
        for (int i = 0; i < 16; i++) sm[PHYS(base + i * 16)] = v[i];
    }
    __syncthreads();

    // ---- pass 2 (bits 8..11) fused with global store ----
    u64* gout = (u64*)g_buf;
#pragma unroll
    for (int gi = 0; gi < 2; gi++) {
        int g = t + gi * 128;
        u64 v[16];
#pragma unroll
        for (int i = 0; i < 16; i++) v[i] = sm[PHYS(g + (i << 8))];
        bstages(v, 2, 1, 0);
#pragma unroll
        for (int i = 0; i < 16; i++)
            gout[(size_t)row * DIM + g + (i << 8)] = v[i];  // coalesced per i
    }
}

// ---------------------------------------------------------------------------
// Kernel B: Z = U Y, TWO adjacent COLUMNS per CTA, 256 threads, 64KB smem.
// min 3 CTAs/SM -> regs capped -> 24 warps/SM.
// Column c lives in sm[c*DIM + (PHYS(r) ^ (c<<2))].
// ---------------------------------------------------------------------------
__global__ void __launch_bounds__(256, 3) kernelB(float* __restrict__ out) {
    extern __shared__ float2 smf[];
    u64* sm = (u64*)smf;                      // [2][DIM]
    const int tid = threadIdx.x;
    const int c0  = blockIdx.x * 2;

    // ---- gather 2 columns ----
#pragma unroll
    for (int it = 0; it < DIM / 256; it++) {  // 16 iters
        int r = it * 256 + tid;
        float4 f = g_buf[((size_t)r * DIM + c0) / 2];
        sm[PHYS(r)]             = pack2(f.x, f.y);
        sm[DIM + (PHYS(r) ^ 4)] = pack2(f.z, f.w);
    }
    __syncthreads();

    const int row = tid >> 7;
    const int t   = tid & 127;
    const int sw  = row << 2;
    u64* srow     = sm + row * DIM;

    // ---- pass 0 ----
#pragma unroll
    for (int gi = 0; gi < 2; gi++) {
        int g = t + gi * 128;
        u64 v[16];
#pragma unroll
        for (int i = 0; i < 16; i++) v[i] = srow[PHYS(g * 16 + i) ^ sw];
        bstages(v, 0, 0, 0);
#pragma unroll
        for (int i = 0; i < 16; i++) srow[PHYS(g * 16 + i) ^ sw] = v[i];
    }
    __syncthreads();

    // ---- pass 1 ----
#pragma unroll
    for (int gi = 0; gi < 2; gi++) {
        int g = t + gi * 128;
        int base = ((g >> 4) << 8) + (g & 15);
        u64 v[16];
#pragma unroll
        for (int i = 0; i < 16; i++) v[i] = srow[PHYS(base + i * 16) ^ sw];
        bstages(v, 1, 0, 0);
#pragma unroll
        for (int i = 0; i < 16; i++) srow[PHYS(base + i * 16) ^ sw] = v[i];
    }
    __syncthreads();

    // ---- pass 2 ----
#pragma unroll
    for (int gi = 0; gi < 2; gi++) {
        int g = t + gi * 128;
        u64 v[16];
#pragma unroll
        for (int i = 0; i < 16; i++) v[i] = srow[PHYS(g + (i << 8)) ^ sw];
        bstages(v, 2, 0, 0);
#pragma unroll
        for (int i = 0; i < 16; i++) srow[PHYS(g + (i << 8)) ^ sw] = v[i];
    }
    __syncthreads();

    // ---- write real(Z) for both columns: 8B per row ----
#pragma unroll
    for (int it = 0; it < DIM / 256; it++) {  // 16 iters
        int r = it * 256 + tid;
        float a = lo32(sm[PHYS(r)]);
        float b = lo32(sm[DIM + (PHYS(r) ^ 4)]);
        *(float2*)(out + (size_t)r * DIM + c0) = make_float2(a, b);
    }
}

// ---------------------------------------------------------------------------
extern "C" void kernel_launch(void* const* d_in, const int* in_sizes, int n_in,
                              void* d_out, int out_size) {
    const float* w;
    const float* x;
    if (in_sizes[0] <= in_sizes[1]) { w = (const float*)d_in[0]; x = (const float*)d_in[1]; }
    else                            { w = (const float*)d_in[1]; x = (const float*)d_in[0]; }

    const int smA = DIM * (int)sizeof(float2);        // 32 KB
    const int smB = 2 * DIM * (int)sizeof(float2);    // 64 KB
    cudaFuncSetAttribute(kernelA, cudaFuncAttributeMaxDynamicSharedMemorySize, smA);
    cudaFuncSetAttribute(kernelB, cudaFuncAttributeMaxDynamicSharedMemorySize, smB);

    prep_kernel<<<1, 32>>>(w);
    kernelA<<<DIM, 128, smA>>>(x);                    // Y = x U^H -> g_buf
    kernelB<<<DIM / 2, 256, smB>>>((float*)d_out);    // Z = U Y   -> real out
}